// round 13
// baseline (speedup 1.0000x reference)
#include <cuda_runtime.h>
#include <cuda_bf16.h>
#include <cstdint>
#include <math.h>

#define NN 200000
#define NE 600000
#define NG 8192
#define DIN 64
#define HD 128
#define NL 4
#define LNEPS 1e-5f
#define NBLK 782              // ceil(NN/256)

#define BUFE (128 * 72)       // elems per smem buffer (row pitch 72 bf16 = 144B, 16B-aligned)
#define GEMM_SMEM (4 * BUFE * (int)sizeof(__nv_bfloat16))   // 2xA + 2xB = 73728 B

// ---------------- scratch (device globals, no allocations) ----------------
__device__ float g_h  [(size_t)NN * HD];
__device__ float g_hw [(size_t)NN * HD];
__device__ float g_gw [(size_t)NG * HD];
__device__ float g_dis[NN];
__device__ int   g_cnt [NN];
__device__ int   g_cur [NN];
__device__ int   g_off [NN + 1];
__device__ int   g_bsum[NBLK];
__device__ int   g_srcs[NE];

__device__ __nv_bfloat16 g_h2  [(size_t)NN * 2 * HD];   // [hi(128) | lo(128)]
__device__ __nv_bfloat16 g_hw2 [(size_t)NN * 2 * HD];
__device__ __nv_bfloat16 g_tmp2[(size_t)NN * 2 * HD];
__device__ __nv_bfloat16 g_x2  [(size_t)NN * 2 * DIN];
__device__ __nv_bfloat16 g_gemb2[(size_t)NG * 2 * HD];

// weights expanded to [hi | lo | hi] along K (3K cols)
__device__ __nv_bfloat16 w3_in  [128 * 3 * DIN];
__device__ __nv_bfloat16 w3_conv[NL * 128 * 3 * HD];
__device__ __nv_bfloat16 w3_p1  [128 * 3 * HD];
__device__ __nv_bfloat16 w3_p2  [128 * 3 * HD];
__device__ __nv_bfloat16 w3_h1a [128 * 3 * HD];
__device__ __nv_bfloat16 w3_h1b [128 * 3 * HD];

// ---------------- CSR build + norms ----------------
__global__ void zero_cnt_kernel() {
    int i = blockIdx.x * blockDim.x + threadIdx.x;
    if (i < NN) { g_cnt[i] = 0; g_cur[i] = 0; }
}
__global__ void hist_kernel(const int* __restrict__ ei) {
    int e = blockIdx.x * blockDim.x + threadIdx.x;
    if (e < NE) atomicAdd(&g_cnt[ei[NE + e]], 1);
}
__global__ void scan1_kernel() {
    int i = blockIdx.x * 256 + threadIdx.x;
    int v = (i < NN) ? g_cnt[i] : 0;
    int x = v;
    int lane = threadIdx.x & 31, wid = threadIdx.x >> 5;
#pragma unroll
    for (int o = 1; o < 32; o <<= 1) {
        int y = __shfl_up_sync(0xffffffffu, x, o);
        if (lane >= o) x += y;
    }
    __shared__ int ws[8];
    if (lane == 31) ws[wid] = x;
    __syncthreads();
    if (threadIdx.x < 8) {
        int w = ws[threadIdx.x];
#pragma unroll
        for (int o = 1; o < 8; o <<= 1) {
            int y = __shfl_up_sync(0xffu, w, o);
            if ((threadIdx.x & 7) >= o) w += y;
        }
        ws[threadIdx.x] = w;
    }
    __syncthreads();
    int excl = x - v + (wid ? ws[wid - 1] : 0);
    if (i < NN) g_off[i] = excl;
    if (threadIdx.x == 255) g_bsum[blockIdx.x] = excl + v;
}
__global__ void scan2_kernel() {
    __shared__ int sh[1024];
    int t = threadIdx.x;
    sh[t] = (t < NBLK) ? g_bsum[t] : 0;
    __syncthreads();
    int lane = t & 31, wid = t >> 5;
    int v = sh[t], x = v;
#pragma unroll
    for (int o = 1; o < 32; o <<= 1) {
        int y = __shfl_up_sync(0xffffffffu, x, o);
        if (lane >= o) x += y;
    }
    __shared__ int ws[32];
    if (lane == 31) ws[wid] = x;
    __syncthreads();
    if (t < 32) {
        int w = ws[t];
#pragma unroll
        for (int o = 1; o < 32; o <<= 1) {
            int y = __shfl_up_sync(0xffffffffu, w, o);
            if (lane >= o) w += y;
        }
        ws[t] = w;
    }
    __syncthreads();
    int excl = x - v + (wid ? ws[wid - 1] : 0);
    if (t < NBLK) g_bsum[t] = excl;
    if (t == 0) g_off[NN] = NE;
}
__global__ void scan3_kernel() {
    int i = blockIdx.x * 256 + threadIdx.x;
    if (i < NN) g_off[i] += g_bsum[blockIdx.x];
}
__global__ void dis_kernel() {
    int i = blockIdx.x * blockDim.x + threadIdx.x;
    if (i < NN) g_dis[i] = rsqrtf((float)g_cnt[i] + 1.f);
}
__global__ void fill_kernel(const int* __restrict__ ei) {
    int e = blockIdx.x * blockDim.x + threadIdx.x;
    if (e >= NE) return;
    int s = ei[e], d = ei[NE + e];
    int pos = g_off[d] + atomicAdd(&g_cur[d], 1);
    g_srcs[pos] = s;
}

// ---------------- conversions ----------------
__device__ __forceinline__ void split_bf16(float v, __nv_bfloat16& hi, __nv_bfloat16& lo) {
    hi = __float2bfloat16(v);
    lo = __float2bfloat16(v - __bfloat162float(hi));
}

__global__ void convert_x_kernel(const float* __restrict__ x) {
    int i = blockIdx.x * blockDim.x + threadIdx.x;
    if (i >= NN * DIN) return;
    int n = i >> 6, k = i & 63;
    __nv_bfloat16 hi, lo;
    split_bf16(x[i], hi, lo);
    g_x2[(size_t)n * 128 + k]      = hi;
    g_x2[(size_t)n * 128 + 64 + k] = lo;
}

__global__ void convert_w_kernel(const float* __restrict__ src, int lds, int K, int rows,
                                 __nv_bfloat16* __restrict__ dst) {
    int i = blockIdx.x * blockDim.x + threadIdx.x;
    if (i >= rows * K) return;
    int j = i / K, k = i - j * K;
    __nv_bfloat16 hi, lo;
    split_bf16(src[(size_t)j * lds + k], hi, lo);
    size_t b = (size_t)j * 3 * K;
    dst[b + k]         = hi;
    dst[b + K + k]     = lo;
    dst[b + 2 * K + k] = hi;
}

// ---------------- cp.async helpers ----------------
__device__ __forceinline__ void cp16(__nv_bfloat16* dst, const __nv_bfloat16* src, bool ok) {
    unsigned d = (unsigned)__cvta_generic_to_shared(dst);
    int sz = ok ? 16 : 0;
    asm volatile("cp.async.cg.shared.global [%0], [%1], 16, %2;"
                 :: "r"(d), "l"(src), "r"(sz));
}
__device__ __forceinline__ void cp_commit() {
    asm volatile("cp.async.commit_group;" ::: "memory");
}
__device__ __forceinline__ void cp_wait0() {
    asm volatile("cp.async.wait_group 0;" ::: "memory");
}

// ---------------- tensor-core GEMM (bf16x3, fp32 accum, cp.async pipelined) ------
__device__ __forceinline__ void mma_bf16(float4& c, unsigned a0, unsigned a1, unsigned a2,
                                         unsigned a3, unsigned b0, unsigned b1) {
    asm volatile(
        "mma.sync.aligned.m16n8k16.row.col.f32.bf16.bf16.f32 "
        "{%0,%1,%2,%3}, {%4,%5,%6,%7}, {%8,%9}, {%0,%1,%2,%3};"
        : "+f"(c.x), "+f"(c.y), "+f"(c.z), "+f"(c.w)
        : "r"(a0), "r"(a1), "r"(a2), "r"(a3), "r"(b0), "r"(b1));
}

template<int K, bool SILU_, bool BIAS, bool GATHER, bool RES, bool WF32, bool WBF>
__launch_bounds__(256)
__global__ void gemm_bf16(const __nv_bfloat16* __restrict__ A2,
                          const __nv_bfloat16* __restrict__ B3,
                          const float* __restrict__ bias,
                          const float* __restrict__ gtab, const int* __restrict__ gidx,
                          const float* __restrict__ Rsrc,
                          float* __restrict__ C, __nv_bfloat16* __restrict__ C2,
                          int nrows)
{
    constexpr int LDA = 2 * K;
    constexpr int LDB = 3 * K;
    constexpr int NC  = (3 * K) / 64;     // 64-wide k chunks

    extern __shared__ __nv_bfloat16 smem[];
    __nv_bfloat16* Asm = smem;                 // 2 buffers of 128x72
    __nv_bfloat16* Bsm = smem + 2 * BUFE;      // 2 buffers of 128x72

    const int t    = threadIdx.x;
    const int lane = t & 31;
    const int wid  = t >> 5;
    const int wm   = wid >> 2;    // 0..1  (64 rows each)
    const int wn   = wid & 3;     // 0..3  (32 cols each)
    const int g    = lane >> 2;   // 0..7
    const int tg   = lane & 3;    // 0..3
    const int rowBase = blockIdx.x * 128;

    float4 acc[4][4];
#pragma unroll
    for (int i = 0; i < 4; i++)
#pragma unroll
        for (int j = 0; j < 4; j++) acc[i][j] = make_float4(0.f, 0.f, 0.f, 0.f);

    auto loadChunk = [&](int c, int buf) {
        const int k0  = c * 64;
        const int seg = k0 / K;
        const int aOff = (seg == 2 ? K : 0) + (k0 - seg * K);   // A: hi,hi,lo
        __nv_bfloat16* Ab = Asm + buf * BUFE;
        __nv_bfloat16* Bb = Bsm + buf * BUFE;
#pragma unroll
        for (int q = 0; q < 4; q++) {
            int f = t + 256 * q;
            int r = f >> 3, sub = f & 7;
            int grow = rowBase + r;
            cp16(&Ab[r * 72 + sub * 8], &A2[(size_t)grow * LDA + aOff + sub * 8], grow < nrows);
            cp16(&Bb[r * 72 + sub * 8], &B3[(size_t)r * LDB + k0 + sub * 8], true);
        }
        cp_commit();
    };

    auto mmas = [&](int buf) {
        const __nv_bfloat16* Ab = Asm + buf * BUFE;
        const __nv_bfloat16* Bb = Bsm + buf * BUFE;
#pragma unroll
        for (int ks = 0; ks < 4; ks++) {
            unsigned a[4][4], b[4][2];
#pragma unroll
            for (int mt = 0; mt < 4; mt++) {
                int rm = wm * 64 + mt * 16;
                a[mt][0] = *reinterpret_cast<const unsigned*>(&Ab[(rm + g    ) * 72 + ks * 16 + tg * 2]);
                a[mt][1] = *reinterpret_cast<const unsigned*>(&Ab[(rm + g + 8) * 72 + ks * 16 + tg * 2]);
                a[mt][2] = *reinterpret_cast<const unsigned*>(&Ab[(rm + g    ) * 72 + ks * 16 + tg * 2 + 8]);
                a[mt][3] = *reinterpret_cast<const unsigned*>(&Ab[(rm + g + 8) * 72 + ks * 16 + tg * 2 + 8]);
            }
#pragma unroll
            for (int nt = 0; nt < 4; nt++) {
                int cn = wn * 32 + nt * 8 + g;
                b[nt][0] = *reinterpret_cast<const unsigned*>(&Bb[cn * 72 + ks * 16 + tg * 2]);
                b[nt][1] = *reinterpret_cast<const unsigned*>(&Bb[cn * 72 + ks * 16 + tg * 2 + 8]);
            }
#pragma unroll
            for (int mt = 0; mt < 4; mt++)
#pragma unroll
                for (int nt = 0; nt < 4; nt++)
                    mma_bf16(acc[mt][nt], a[mt][0], a[mt][1], a[mt][2], a[mt][3],
                             b[nt][0], b[nt][1]);
        }
    };

    // pipelined mainloop: one sync per chunk, loads of c+1 overlap mma of c
    loadChunk(0, 0);
#pragma unroll
    for (int c = 0; c < NC; c++) {
        cp_wait0();
        __syncthreads();
        if (c + 1 < NC) loadChunk(c + 1, (c + 1) & 1);
        mmas(c & 1);
    }

    // epilogue
#pragma unroll
    for (int mt = 0; mt < 4; mt++) {
#pragma unroll
        for (int hh = 0; hh < 2; hh++) {
            int row = rowBase + wm * 64 + mt * 16 + g + hh * 8;
            if (row >= nrows) continue;
            int gi = 0;
            if (GATHER) gi = gidx[row];
#pragma unroll
            for (int nt = 0; nt < 4; nt++) {
                int col = wn * 32 + nt * 8 + tg * 2;
                float v0 = hh ? acc[mt][nt].z : acc[mt][nt].x;
                float v1 = hh ? acc[mt][nt].w : acc[mt][nt].y;
                if (BIAS) {
                    float2 bv = *reinterpret_cast<const float2*>(&bias[col]);
                    v0 += bv.x; v1 += bv.y;
                }
                if (GATHER) {
                    float2 gv = *reinterpret_cast<const float2*>(&gtab[(size_t)gi * 128 + col]);
                    v0 += gv.x; v1 += gv.y;
                }
                if (RES) {
                    float2 rv = *reinterpret_cast<const float2*>(&Rsrc[(size_t)row * 128 + col]);
                    v0 += rv.x; v1 += rv.y;
                }
                if (SILU_) {
                    v0 = v0 / (1.f + expf(-v0));
                    v1 = v1 / (1.f + expf(-v1));
                }
                if (WF32)
                    *reinterpret_cast<float2*>(&C[(size_t)row * 128 + col]) = make_float2(v0, v1);
                if (WBF) {
                    __nv_bfloat16 h0, l0, h1, l1;
                    split_bf16(v0, h0, l0);
                    split_bf16(v1, h1, l1);
                    *reinterpret_cast<__nv_bfloat162*>(&C2[(size_t)row * 256 + col]) =
                        __halves2bfloat162(h0, h1);
                    *reinterpret_cast<__nv_bfloat162*>(&C2[(size_t)row * 256 + 128 + col]) =
                        __halves2bfloat162(l0, l1);
                }
            }
        }
    }
}

// ---------------- fused: agg (CSR gather) + silu + LN + residual ----------------
__global__ void agg_silu_ln_kernel(const float* __restrict__ cb,
                                   const float* __restrict__ lng,
                                   const float* __restrict__ lnb) {
    int d = (blockIdx.x * blockDim.x + threadIdx.x) >> 5;
    int lane = threadIdx.x & 31;
    if (d >= NN) return;
    size_t base = (size_t)d * HD + lane * 4;
    float dd = g_dis[d];
    float sn = dd * dd;
    float4 acc = *reinterpret_cast<const float4*>(&g_hw[base]);
    float4 cb4 = *reinterpret_cast<const float4*>(&cb[lane * 4]);
    acc.x = acc.x * sn + cb4.x; acc.y = acc.y * sn + cb4.y;
    acc.z = acc.z * sn + cb4.z; acc.w = acc.w * sn + cb4.w;
    int beg = g_off[d], end = g_off[d + 1];
    for (int e = beg; e < end; e++) {
        int s = g_srcs[e];
        float ne = g_dis[s] * dd;
        float4 v = *reinterpret_cast<const float4*>(&g_hw[(size_t)s * HD + lane * 4]);
        acc.x += v.x * ne; acc.y += v.y * ne; acc.z += v.z * ne; acc.w += v.w * ne;
    }
    float4 s4;
    s4.x = acc.x / (1.f + expf(-acc.x));
    s4.y = acc.y / (1.f + expf(-acc.y));
    s4.z = acc.z / (1.f + expf(-acc.z));
    s4.w = acc.w / (1.f + expf(-acc.w));
    float sum = s4.x + s4.y + s4.z + s4.w;
#pragma unroll
    for (int o = 16; o; o >>= 1) sum += __shfl_xor_sync(0xFFFFFFFFu, sum, o);
    float mu = sum * (1.f / HD);
    float dx = s4.x - mu, dy = s4.y - mu, dz = s4.z - mu, dw = s4.w - mu;
    float sq = dx * dx + dy * dy + dz * dz + dw * dw;
#pragma unroll
    for (int o = 16; o; o >>= 1) sq += __shfl_xor_sync(0xFFFFFFFFu, sq, o);
    float r = rsqrtf(sq * (1.f / HD) + LNEPS);
    float4 g4 = *reinterpret_cast<const float4*>(&lng[lane * 4]);
    float4 b4 = *reinterpret_cast<const float4*>(&lnb[lane * 4]);
    float4 h = *reinterpret_cast<const float4*>(&g_h[base]);
    h.x += dx * r * g4.x + b4.x;
    h.y += dy * r * g4.y + b4.y;
    h.z += dz * r * g4.z + b4.z;
    h.w += dw * r * g4.w + b4.w;
    *reinterpret_cast<float4*>(&g_h[base]) = h;
    __nv_bfloat16 hi0, lo0, hi1, lo1, hi2, lo2, hi3, lo3;
    split_bf16(h.x, hi0, lo0); split_bf16(h.y, hi1, lo1);
    split_bf16(h.z, hi2, lo2); split_bf16(h.w, hi3, lo3);
    size_t b2 = (size_t)d * 256 + lane * 4;
    *reinterpret_cast<__nv_bfloat162*>(&g_h2[b2])           = __halves2bfloat162(hi0, hi1);
    *reinterpret_cast<__nv_bfloat162*>(&g_h2[b2 + 2])       = __halves2bfloat162(hi2, hi3);
    *reinterpret_cast<__nv_bfloat162*>(&g_h2[b2 + 128])     = __halves2bfloat162(lo0, lo1);
    *reinterpret_cast<__nv_bfloat162*>(&g_h2[b2 + 128 + 2]) = __halves2bfloat162(lo2, lo3);
}

// ---------------- graph mean pool (batch_vec sorted; one block per graph) --------
__global__ void pool_kernel(const int* __restrict__ bv) {
    int g = blockIdx.x;
    int j = threadIdx.x;
    __shared__ int se[2];
    if (j < 2) {
        int target = g + j;
        int lo = 0, hi = NN;
        while (lo < hi) { int m = (lo + hi) >> 1; if (bv[m] < target) lo = m + 1; else hi = m; }
        se[j] = lo;
    }
    __syncthreads();
    int s = se[0], e = se[1];
    float acc = 0.f;
    for (int r = s; r < e; r++) acc += g_h[(size_t)r * HD + j];
    float c = (float)(e - s);
    float v = acc / fmaxf(c, 1.f);
    __nv_bfloat16 hi, lo;
    split_bf16(v, hi, lo);
    g_gemb2[(size_t)g * 256 + j]       = hi;
    g_gemb2[(size_t)g * 256 + 128 + j] = lo;
}

// ---------------- final projection to scalar (warp per row) ----------------
__global__ void head_out_kernel(const float* __restrict__ w2, const float* __restrict__ b2,
                                float* __restrict__ out) {
    int row = (blockIdx.x * blockDim.x + threadIdx.x) >> 5;
    int lane = threadIdx.x & 31;
    if (row >= NN) return;
    float4 v = *reinterpret_cast<const float4*>(&g_hw[(size_t)row * HD + lane * 4]);
    float4 u = *reinterpret_cast<const float4*>(&w2[lane * 4]);
    float s = v.x * u.x + v.y * u.y + v.z * u.z + v.w * u.w;
#pragma unroll
    for (int o = 16; o; o >>= 1) s += __shfl_xor_sync(0xFFFFFFFFu, s, o);
    if (lane == 0) out[row] = s + b2[0];
}

// ---------------- launch ----------------
extern "C" void kernel_launch(void* const* d_in, const int* in_sizes, int n_in,
                              void* d_out, int out_size) {
    const float* x       = (const float*)d_in[0];
    const int*   ei      = (const int*)  d_in[1];
    const int*   bv      = (const int*)  d_in[2];
    const float* in_w    = (const float*)d_in[3];
    const float* in_b    = (const float*)d_in[4];
    const float* conv_w  = (const float*)d_in[5];
    const float* conv_b  = (const float*)d_in[6];
    const float* ln_g    = (const float*)d_in[7];
    const float* ln_b    = (const float*)d_in[8];
    const float* phys_w1 = (const float*)d_in[9];
    const float* phys_b1 = (const float*)d_in[10];
    const float* phys_w2 = (const float*)d_in[11];
    const float* phys_b2 = (const float*)d_in[12];
    const float* head_w1 = (const float*)d_in[13];
    const float* head_b1 = (const float*)d_in[14];
    const float* head_w2 = (const float*)d_in[15];
    const float* head_b2 = (const float*)d_in[16];
    float* out = (float*)d_out;

    float *p_h, *p_hw, *p_gw;
    __nv_bfloat16 *p_h2, *p_hw2, *p_tmp2, *p_x2, *p_gemb2;
    __nv_bfloat16 *p_w3in, *p_w3conv, *p_w3p1, *p_w3p2, *p_w3h1a, *p_w3h1b;
    cudaGetSymbolAddress((void**)&p_h,     g_h);
    cudaGetSymbolAddress((void**)&p_hw,    g_hw);
    cudaGetSymbolAddress((void**)&p_gw,    g_gw);
    cudaGetSymbolAddress((void**)&p_h2,    g_h2);
    cudaGetSymbolAddress((void**)&p_hw2,   g_hw2);
    cudaGetSymbolAddress((void**)&p_tmp2,  g_tmp2);
    cudaGetSymbolAddress((void**)&p_x2,    g_x2);
    cudaGetSymbolAddress((void**)&p_gemb2, g_gemb2);
    cudaGetSymbolAddress((void**)&p_w3in,  w3_in);
    cudaGetSymbolAddress((void**)&p_w3conv,w3_conv);
    cudaGetSymbolAddress((void**)&p_w3p1,  w3_p1);
    cudaGetSymbolAddress((void**)&p_w3p2,  w3_p2);
    cudaGetSymbolAddress((void**)&p_w3h1a, w3_h1a);
    cudaGetSymbolAddress((void**)&p_w3h1b, w3_h1b);

    // allow 72KB dynamic smem for every gemm instantiation we launch
    cudaFuncSetAttribute(gemm_bf16<DIN, false, true, false, false, true, true>,
                         cudaFuncAttributeMaxDynamicSharedMemorySize, GEMM_SMEM);
    cudaFuncSetAttribute(gemm_bf16<HD, false, false, false, false, true, false>,
                         cudaFuncAttributeMaxDynamicSharedMemorySize, GEMM_SMEM);
    cudaFuncSetAttribute(gemm_bf16<HD, true, true, false, false, false, true>,
                         cudaFuncAttributeMaxDynamicSharedMemorySize, GEMM_SMEM);
    cudaFuncSetAttribute(gemm_bf16<HD, false, true, false, true, false, true>,
                         cudaFuncAttributeMaxDynamicSharedMemorySize, GEMM_SMEM);
    cudaFuncSetAttribute(gemm_bf16<HD, true, true, true, false, true, false>,
                         cudaFuncAttributeMaxDynamicSharedMemorySize, GEMM_SMEM);

    const int GEMM_GRID = (NN + 127) / 128;          // 1563
    const int WCONV_GRID = (128 * HD + 255) / 256;

    // CSR build + norms
    zero_cnt_kernel<<<(NN + 255) / 256, 256>>>();
    hist_kernel<<<(NE + 255) / 256, 256>>>(ei);
    scan1_kernel<<<NBLK, 256>>>();
    scan2_kernel<<<1, 1024>>>();
    scan3_kernel<<<NBLK, 256>>>();
    dis_kernel<<<(NN + 255) / 256, 256>>>();
    fill_kernel<<<(NE + 255) / 256, 256>>>(ei);

    // conversions
    convert_x_kernel<<<(NN * DIN + 255) / 256, 256>>>(x);
    convert_w_kernel<<<(128 * DIN + 255) / 256, 256>>>(in_w, DIN, DIN, 128, p_w3in);
    for (int l = 0; l < NL; l++)
        convert_w_kernel<<<WCONV_GRID, 256>>>(conv_w + (size_t)l * HD * HD, HD, HD, 128,
                                              p_w3conv + (size_t)l * 128 * 3 * HD);
    convert_w_kernel<<<WCONV_GRID, 256>>>(phys_w1, HD, HD, 128, p_w3p1);
    convert_w_kernel<<<WCONV_GRID, 256>>>(phys_w2, HD, HD, 128, p_w3p2);
    convert_w_kernel<<<WCONV_GRID, 256>>>(head_w1,      2 * HD, HD, 128, p_w3h1a);
    convert_w_kernel<<<WCONV_GRID, 256>>>(head_w1 + HD, 2 * HD, HD, 128, p_w3h1b);

    // input projection: h = x @ in_w.T + in_b  (write f32 + bf16)
    gemm_bf16<DIN, false, true, false, false, true, true><<<GEMM_GRID, 256, GEMM_SMEM>>>(
        p_x2, p_w3in, in_b, nullptr, nullptr, nullptr, p_h, p_h2, NN);

    // GCN layers: GEMM (hw = h@W.T, f32 only) then fused CSR-agg + silu + LN + residual
    for (int l = 0; l < NL; l++) {
        gemm_bf16<HD, false, false, false, false, true, false><<<GEMM_GRID, 256, GEMM_SMEM>>>(
            p_h2, p_w3conv + (size_t)l * 128 * 3 * HD, nullptr,
            nullptr, nullptr, nullptr, p_hw, nullptr, NN);
        agg_silu_ln_kernel<<<(NN + 7) / 8, 256>>>(conv_b + l * HD, ln_g + l * HD, ln_b + l * HD);
    }

    // graph mean pooling over final h
    pool_kernel<<<NG, 128>>>(bv);

    // physics MLP: hw2 = silu(h@W1.T+b1) (bf16 only)
    gemm_bf16<HD, true, true, false, false, false, true><<<GEMM_GRID, 256, GEMM_SMEM>>>(
        p_h2, p_w3p1, phys_b1, nullptr, nullptr, nullptr, nullptr, p_hw2, NN);
    // tmp2 = h + hw@W2.T + b2 (bf16 only)
    gemm_bf16<HD, false, true, false, true, false, true><<<GEMM_GRID, 256, GEMM_SMEM>>>(
        p_hw2, p_w3p2, phys_b2, nullptr, nullptr, p_h, nullptr, p_tmp2, NN);

    // per-graph precompute: gw = graph_emb @ W1b.T
    gemm_bf16<HD, false, false, false, false, true, false><<<NG / 128, 256, GEMM_SMEM>>>(
        p_gemb2, p_w3h1b, nullptr, nullptr, nullptr, nullptr, p_gw, nullptr, NG);

    // hid = silu( tmp @ W1a.T + gw[batch] + b1 )  -> g_hw (f32)
    gemm_bf16<HD, true, true, true, false, true, false><<<GEMM_GRID, 256, GEMM_SMEM>>>(
        p_tmp2, p_w3h1a, head_b1, p_gw, bv, nullptr, p_hw, nullptr, NN);

    // out = hid @ w2.T + b2
    head_out_kernel<<<(NN + 7) / 8, 256>>>(head_w2, head_b2, out);
}

// round 15
// speedup vs baseline: 1.1131x; 1.1131x over previous
#include <cuda_runtime.h>
#include <cuda_bf16.h>
#include <cstdint>
#include <math.h>

#define NN 200000
#define NE 600000
#define NG 8192
#define DIN 64
#define HD 128
#define NL 4
#define LNEPS 1e-5f
#define NBLK 782              // ceil(NN/256)

// ---------------- scratch (device globals, no allocations) ----------------
__device__ float g_h  [(size_t)NN * HD];
__device__ float g_hw [(size_t)NN * HD];
__device__ float g_gw [(size_t)NG * HD];
__device__ float g_dis[NN];
__device__ int   g_cnt [NN];
__device__ int   g_cur [NN];
__device__ int   g_off [NN + 1];
__device__ int   g_bsum[NBLK];
__device__ int   g_srcs[NE];

__device__ __nv_bfloat16 g_h2  [(size_t)NN * 2 * HD];   // [hi(128) | lo(128)]
__device__ __nv_bfloat16 g_hw2 [(size_t)NN * 2 * HD];
__device__ __nv_bfloat16 g_tmp2[(size_t)NN * 2 * HD];
__device__ __nv_bfloat16 g_x2  [(size_t)NN * 2 * DIN];
__device__ __nv_bfloat16 g_gemb2[(size_t)NG * 2 * HD];

// weights expanded to [hi | lo | hi] along K (3K cols)
__device__ __nv_bfloat16 w3_in  [128 * 3 * DIN];
__device__ __nv_bfloat16 w3_conv[NL * 128 * 3 * HD];
__device__ __nv_bfloat16 w3_p1  [128 * 3 * HD];
__device__ __nv_bfloat16 w3_p2  [128 * 3 * HD];
__device__ __nv_bfloat16 w3_h1a [128 * 3 * HD];
__device__ __nv_bfloat16 w3_h1b [128 * 3 * HD];

// ---------------- CSR build + norms ----------------
__global__ void zero_cnt_kernel() {
    int i = blockIdx.x * blockDim.x + threadIdx.x;
    if (i < NN) { g_cnt[i] = 0; g_cur[i] = 0; }
}
__global__ void hist_kernel(const int* __restrict__ ei) {
    int e = blockIdx.x * blockDim.x + threadIdx.x;
    if (e < NE) atomicAdd(&g_cnt[ei[NE + e]], 1);
}
__global__ void scan1_kernel() {
    int i = blockIdx.x * 256 + threadIdx.x;
    int v = (i < NN) ? g_cnt[i] : 0;
    int x = v;
    int lane = threadIdx.x & 31, wid = threadIdx.x >> 5;
#pragma unroll
    for (int o = 1; o < 32; o <<= 1) {
        int y = __shfl_up_sync(0xffffffffu, x, o);
        if (lane >= o) x += y;
    }
    __shared__ int ws[8];
    if (lane == 31) ws[wid] = x;
    __syncthreads();
    if (threadIdx.x < 8) {
        int w = ws[threadIdx.x];
#pragma unroll
        for (int o = 1; o < 8; o <<= 1) {
            int y = __shfl_up_sync(0xffu, w, o);
            if ((threadIdx.x & 7) >= o) w += y;
        }
        ws[threadIdx.x] = w;
    }
    __syncthreads();
    int excl = x - v + (wid ? ws[wid - 1] : 0);
    if (i < NN) g_off[i] = excl;
    if (threadIdx.x == 255) g_bsum[blockIdx.x] = excl + v;
}
__global__ void scan2_kernel() {
    __shared__ int sh[1024];
    int t = threadIdx.x;
    sh[t] = (t < NBLK) ? g_bsum[t] : 0;
    __syncthreads();
    int lane = t & 31, wid = t >> 5;
    int v = sh[t], x = v;
#pragma unroll
    for (int o = 1; o < 32; o <<= 1) {
        int y = __shfl_up_sync(0xffffffffu, x, o);
        if (lane >= o) x += y;
    }
    __shared__ int ws[32];
    if (lane == 31) ws[wid] = x;
    __syncthreads();
    if (t < 32) {
        int w = ws[t];
#pragma unroll
        for (int o = 1; o < 32; o <<= 1) {
            int y = __shfl_up_sync(0xffffffffu, w, o);
            if (lane >= o) w += y;
        }
        ws[t] = w;
    }
    __syncthreads();
    int excl = x - v + (wid ? ws[wid - 1] : 0);
    if (t < NBLK) g_bsum[t] = excl;
    if (t == 0) g_off[NN] = NE;
}
__global__ void scan3_kernel() {
    int i = blockIdx.x * 256 + threadIdx.x;
    if (i < NN) g_off[i] += g_bsum[blockIdx.x];
}
__global__ void dis_kernel() {
    int i = blockIdx.x * blockDim.x + threadIdx.x;
    if (i < NN) g_dis[i] = rsqrtf((float)g_cnt[i] + 1.f);
}
__global__ void fill_kernel(const int* __restrict__ ei) {
    int e = blockIdx.x * blockDim.x + threadIdx.x;
    if (e >= NE) return;
    int s = ei[e], d = ei[NE + e];
    int pos = g_off[d] + atomicAdd(&g_cur[d], 1);
    g_srcs[pos] = s;
}

// ---------------- conversions ----------------
__device__ __forceinline__ void split_bf16(float v, __nv_bfloat16& hi, __nv_bfloat16& lo) {
    hi = __float2bfloat16(v);
    lo = __float2bfloat16(v - __bfloat162float(hi));
}

__global__ void convert_x_kernel(const float* __restrict__ x) {
    int i = blockIdx.x * blockDim.x + threadIdx.x;
    if (i >= NN * DIN) return;
    int n = i >> 6, k = i & 63;
    __nv_bfloat16 hi, lo;
    split_bf16(x[i], hi, lo);
    g_x2[(size_t)n * 128 + k]      = hi;
    g_x2[(size_t)n * 128 + 64 + k] = lo;
}

__global__ void convert_w_kernel(const float* __restrict__ src, int lds, int K, int rows,
                                 __nv_bfloat16* __restrict__ dst) {
    int i = blockIdx.x * blockDim.x + threadIdx.x;
    if (i >= rows * K) return;
    int j = i / K, k = i - j * K;
    __nv_bfloat16 hi, lo;
    split_bf16(src[(size_t)j * lds + k], hi, lo);
    size_t b = (size_t)j * 3 * K;
    dst[b + k]         = hi;
    dst[b + K + k]     = lo;
    dst[b + 2 * K + k] = hi;
}

// ---------------- ldmatrix / mma helpers ----------------
__device__ __forceinline__ unsigned s2u(const void* p) {
    return (unsigned)__cvta_generic_to_shared(p);
}
__device__ __forceinline__ void ldsm_x4(unsigned& d0, unsigned& d1, unsigned& d2, unsigned& d3,
                                        unsigned a) {
    asm volatile("ldmatrix.sync.aligned.m8n8.x4.shared.b16 {%0,%1,%2,%3}, [%4];"
                 : "=r"(d0), "=r"(d1), "=r"(d2), "=r"(d3) : "r"(a));
}
__device__ __forceinline__ void ldsm_x2(unsigned& d0, unsigned& d1, unsigned a) {
    asm volatile("ldmatrix.sync.aligned.m8n8.x2.shared.b16 {%0,%1}, [%2];"
                 : "=r"(d0), "=r"(d1) : "r"(a));
}
__device__ __forceinline__ void mma_bf16(float4& c, unsigned a0, unsigned a1, unsigned a2,
                                         unsigned a3, unsigned b0, unsigned b1) {
    asm volatile(
        "mma.sync.aligned.m16n8k16.row.col.f32.bf16.bf16.f32 "
        "{%0,%1,%2,%3}, {%4,%5,%6,%7}, {%8,%9}, {%0,%1,%2,%3};"
        : "+f"(c.x), "+f"(c.y), "+f"(c.z), "+f"(c.w)
        : "r"(a0), "r"(a1), "r"(a2), "r"(a3), "r"(b0), "r"(b1));
}

// ---------------- tensor-core GEMM (bf16x3, fp32 accum) ----------------
template<int K, bool SILU_, bool BIAS, bool GATHER, bool RES, bool WF32, bool WBF>
__launch_bounds__(256)
__global__ void gemm_bf16(const __nv_bfloat16* __restrict__ A2,
                          const __nv_bfloat16* __restrict__ B3,
                          const float* __restrict__ bias,
                          const float* __restrict__ gtab, const int* __restrict__ gidx,
                          const float* __restrict__ Rsrc,
                          float* __restrict__ C, __nv_bfloat16* __restrict__ C2,
                          int nrows)
{
    constexpr int LDA = 2 * K;
    constexpr int LDB = 3 * K;
    constexpr int NC  = (3 * K) / 64;     // 64-wide k chunks

    __shared__ __nv_bfloat16 As[128][72];
    __shared__ __nv_bfloat16 Bs[128][72];

    const int t    = threadIdx.x;
    const int lane = t & 31;
    const int wid  = t >> 5;
    const int wm   = wid >> 2;    // 0..1  (64 rows each)
    const int wn   = wid & 3;     // 0..3  (32 cols each)
    const int g    = lane >> 2;   // 0..7
    const int tg   = lane & 3;    // 0..3
    const int r8   = lane & 7;    // ldmatrix row within 8x8 tile
    const int mq   = lane >> 3;   // ldmatrix matrix quadrant 0..3
    const int rowBase = blockIdx.x * 128;

    float4 acc[4][4];
#pragma unroll
    for (int i = 0; i < 4; i++)
#pragma unroll
        for (int j = 0; j < 4; j++) acc[i][j] = make_float4(0.f, 0.f, 0.f, 0.f);

    for (int c = 0; c < NC; c++) {
        const int k0  = c * 64;
        const int seg = k0 / K;
        const int aOff = (seg == 2 ? K : 0) + (k0 - seg * K);   // A: hi,hi,lo
#pragma unroll
        for (int q = 0; q < 4; q++) {
            int f = t + 256 * q;
            int r = f >> 3, sub = f & 7;
            uint4 v = make_uint4(0u, 0u, 0u, 0u);
            int grow = rowBase + r;
            if (grow < nrows)
                v = *reinterpret_cast<const uint4*>(&A2[(size_t)grow * LDA + aOff + sub * 8]);
            *reinterpret_cast<uint4*>(&As[r][sub * 8]) = v;
            uint4 w = *reinterpret_cast<const uint4*>(&B3[(size_t)r * LDB + k0 + sub * 8]);
            *reinterpret_cast<uint4*>(&Bs[r][sub * 8]) = w;
        }
        __syncthreads();
#pragma unroll
        for (int ks = 0; ks < 4; ks++) {
            unsigned a[4][4], b[4][2];
#pragma unroll
            for (int mt = 0; mt < 4; mt++) {
                int rm = wm * 64 + mt * 16;
                // x4: mat0 rows rm..+7 k0-7 | mat1 rows rm+8..+15 k0-7 | mat2 rows rm..+7 k8-15 | mat3 rows rm+8..+15 k8-15
                unsigned addr = s2u(&As[rm + ((mq & 1) << 3) + r8][ks * 16 + ((mq >> 1) << 3)]);
                ldsm_x4(a[mt][0], a[mt][1], a[mt][2], a[mt][3], addr);
            }
#pragma unroll
            for (int nt = 0; nt < 4; nt++) {
                int cn0 = wn * 32 + nt * 8;
                // x2: mat0 rows cn0..+7 k0-7 | mat1 rows cn0..+7 k8-15 (lanes 16-31 addrs unused)
                unsigned addr = s2u(&Bs[cn0 + r8][ks * 16 + ((mq & 1) << 3)]);
                ldsm_x2(b[nt][0], b[nt][1], addr);
            }
#pragma unroll
            for (int mt = 0; mt < 4; mt++)
#pragma unroll
                for (int nt = 0; nt < 4; nt++)
                    mma_bf16(acc[mt][nt], a[mt][0], a[mt][1], a[mt][2], a[mt][3],
                             b[nt][0], b[nt][1]);
        }
        __syncthreads();
    }

    // epilogue
#pragma unroll
    for (int mt = 0; mt < 4; mt++) {
#pragma unroll
        for (int hh = 0; hh < 2; hh++) {
            int row = rowBase + wm * 64 + mt * 16 + g + hh * 8;
            if (row >= nrows) continue;
            int gi = 0;
            if (GATHER) gi = gidx[row];
#pragma unroll
            for (int nt = 0; nt < 4; nt++) {
                int col = wn * 32 + nt * 8 + tg * 2;
                float v0 = hh ? acc[mt][nt].z : acc[mt][nt].x;
                float v1 = hh ? acc[mt][nt].w : acc[mt][nt].y;
                if (BIAS) {
                    float2 bv = *reinterpret_cast<const float2*>(&bias[col]);
                    v0 += bv.x; v1 += bv.y;
                }
                if (GATHER) {
                    float2 gv = *reinterpret_cast<const float2*>(&gtab[(size_t)gi * 128 + col]);
                    v0 += gv.x; v1 += gv.y;
                }
                if (RES) {
                    float2 rv = *reinterpret_cast<const float2*>(&Rsrc[(size_t)row * 128 + col]);
                    v0 += rv.x; v1 += rv.y;
                }
                if (SILU_) {
                    v0 = v0 / (1.f + expf(-v0));
                    v1 = v1 / (1.f + expf(-v1));
                }
                if (WF32)
                    *reinterpret_cast<float2*>(&C[(size_t)row * 128 + col]) = make_float2(v0, v1);
                if (WBF) {
                    __nv_bfloat16 h0, l0, h1, l1;
                    split_bf16(v0, h0, l0);
                    split_bf16(v1, h1, l1);
                    *reinterpret_cast<__nv_bfloat162*>(&C2[(size_t)row * 256 + col]) =
                        __halves2bfloat162(h0, h1);
                    *reinterpret_cast<__nv_bfloat162*>(&C2[(size_t)row * 256 + 128 + col]) =
                        __halves2bfloat162(l0, l1);
                }
            }
        }
    }
}

// ---------------- fused: agg (CSR gather) + silu + LN + residual ----------------
__global__ void agg_silu_ln_kernel(const float* __restrict__ cb,
                                   const float* __restrict__ lng,
                                   const float* __restrict__ lnb) {
    int d = (blockIdx.x * blockDim.x + threadIdx.x) >> 5;
    int lane = threadIdx.x & 31;
    if (d >= NN) return;
    size_t base = (size_t)d * HD + lane * 4;
    float dd = g_dis[d];
    float sn = dd * dd;
    float4 acc = *reinterpret_cast<const float4*>(&g_hw[base]);
    float4 cb4 = *reinterpret_cast<const float4*>(&cb[lane * 4]);
    acc.x = acc.x * sn + cb4.x; acc.y = acc.y * sn + cb4.y;
    acc.z = acc.z * sn + cb4.z; acc.w = acc.w * sn + cb4.w;
    int beg = g_off[d], end = g_off[d + 1];
    for (int e = beg; e < end; e++) {
        int s = g_srcs[e];
        float ne = g_dis[s] * dd;
        float4 v = *reinterpret_cast<const float4*>(&g_hw[(size_t)s * HD + lane * 4]);
        acc.x += v.x * ne; acc.y += v.y * ne; acc.z += v.z * ne; acc.w += v.w * ne;
    }
    float4 s4;
    s4.x = acc.x / (1.f + expf(-acc.x));
    s4.y = acc.y / (1.f + expf(-acc.y));
    s4.z = acc.z / (1.f + expf(-acc.z));
    s4.w = acc.w / (1.f + expf(-acc.w));
    float sum = s4.x + s4.y + s4.z + s4.w;
#pragma unroll
    for (int o = 16; o; o >>= 1) sum += __shfl_xor_sync(0xFFFFFFFFu, sum, o);
    float mu = sum * (1.f / HD);
    float dx = s4.x - mu, dy = s4.y - mu, dz = s4.z - mu, dw = s4.w - mu;
    float sq = dx * dx + dy * dy + dz * dz + dw * dw;
#pragma unroll
    for (int o = 16; o; o >>= 1) sq += __shfl_xor_sync(0xFFFFFFFFu, sq, o);
    float r = rsqrtf(sq * (1.f / HD) + LNEPS);
    float4 g4 = *reinterpret_cast<const float4*>(&lng[lane * 4]);
    float4 b4 = *reinterpret_cast<const float4*>(&lnb[lane * 4]);
    float4 h = *reinterpret_cast<const float4*>(&g_h[base]);
    h.x += dx * r * g4.x + b4.x;
    h.y += dy * r * g4.y + b4.y;
    h.z += dz * r * g4.z + b4.z;
    h.w += dw * r * g4.w + b4.w;
    *reinterpret_cast<float4*>(&g_h[base]) = h;
    __nv_bfloat16 hi0, lo0, hi1, lo1, hi2, lo2, hi3, lo3;
    split_bf16(h.x, hi0, lo0); split_bf16(h.y, hi1, lo1);
    split_bf16(h.z, hi2, lo2); split_bf16(h.w, hi3, lo3);
    size_t b2 = (size_t)d * 256 + lane * 4;
    *reinterpret_cast<__nv_bfloat162*>(&g_h2[b2])           = __halves2bfloat162(hi0, hi1);
    *reinterpret_cast<__nv_bfloat162*>(&g_h2[b2 + 2])       = __halves2bfloat162(hi2, hi3);
    *reinterpret_cast<__nv_bfloat162*>(&g_h2[b2 + 128])     = __halves2bfloat162(lo0, lo1);
    *reinterpret_cast<__nv_bfloat162*>(&g_h2[b2 + 128 + 2]) = __halves2bfloat162(lo2, lo3);
}

// ---------------- graph mean pool (batch_vec sorted; one block per graph) --------
__global__ void pool_kernel(const int* __restrict__ bv) {
    int g = blockIdx.x;
    int j = threadIdx.x;
    __shared__ int se[2];
    if (j < 2) {
        int target = g + j;
        int lo = 0, hi = NN;
        while (lo < hi) { int m = (lo + hi) >> 1; if (bv[m] < target) lo = m + 1; else hi = m; }
        se[j] = lo;
    }
    __syncthreads();
    int s = se[0], e = se[1];
    float acc = 0.f;
    for (int r = s; r < e; r++) acc += g_h[(size_t)r * HD + j];
    float c = (float)(e - s);
    float v = acc / fmaxf(c, 1.f);
    __nv_bfloat16 hi, lo;
    split_bf16(v, hi, lo);
    g_gemb2[(size_t)g * 256 + j]       = hi;
    g_gemb2[(size_t)g * 256 + 128 + j] = lo;
}

// ---------------- final projection to scalar (warp per row) ----------------
__global__ void head_out_kernel(const float* __restrict__ w2, const float* __restrict__ b2,
                                float* __restrict__ out) {
    int row = (blockIdx.x * blockDim.x + threadIdx.x) >> 5;
    int lane = threadIdx.x & 31;
    if (row >= NN) return;
    float4 v = *reinterpret_cast<const float4*>(&g_hw[(size_t)row * HD + lane * 4]);
    float4 u = *reinterpret_cast<const float4*>(&w2[lane * 4]);
    float s = v.x * u.x + v.y * u.y + v.z * u.z + v.w * u.w;
#pragma unroll
    for (int o = 16; o; o >>= 1) s += __shfl_xor_sync(0xFFFFFFFFu, s, o);
    if (lane == 0) out[row] = s + b2[0];
}

// ---------------- launch ----------------
extern "C" void kernel_launch(void* const* d_in, const int* in_sizes, int n_in,
                              void* d_out, int out_size) {
    const float* x       = (const float*)d_in[0];
    const int*   ei      = (const int*)  d_in[1];
    const int*   bv      = (const int*)  d_in[2];
    const float* in_w    = (const float*)d_in[3];
    const float* in_b    = (const float*)d_in[4];
    const float* conv_w  = (const float*)d_in[5];
    const float* conv_b  = (const float*)d_in[6];
    const float* ln_g    = (const float*)d_in[7];
    const float* ln_b    = (const float*)d_in[8];
    const float* phys_w1 = (const float*)d_in[9];
    const float* phys_b1 = (const float*)d_in[10];
    const float* phys_w2 = (const float*)d_in[11];
    const float* phys_b2 = (const float*)d_in[12];
    const float* head_w1 = (const float*)d_in[13];
    const float* head_b1 = (const float*)d_in[14];
    const float* head_w2 = (const float*)d_in[15];
    const float* head_b2 = (const float*)d_in[16];
    float* out = (float*)d_out;

    float *p_h, *p_hw, *p_gw;
    __nv_bfloat16 *p_h2, *p_hw2, *p_tmp2, *p_x2, *p_gemb2;
    __nv_bfloat16 *p_w3in, *p_w3conv, *p_w3p1, *p_w3p2, *p_w3h1a, *p_w3h1b;
    cudaGetSymbolAddress((void**)&p_h,     g_h);
    cudaGetSymbolAddress((void**)&p_hw,    g_hw);
    cudaGetSymbolAddress((void**)&p_gw,    g_gw);
    cudaGetSymbolAddress((void**)&p_h2,    g_h2);
    cudaGetSymbolAddress((void**)&p_hw2,   g_hw2);
    cudaGetSymbolAddress((void**)&p_tmp2,  g_tmp2);
    cudaGetSymbolAddress((void**)&p_x2,    g_x2);
    cudaGetSymbolAddress((void**)&p_gemb2, g_gemb2);
    cudaGetSymbolAddress((void**)&p_w3in,  w3_in);
    cudaGetSymbolAddress((void**)&p_w3conv,w3_conv);
    cudaGetSymbolAddress((void**)&p_w3p1,  w3_p1);
    cudaGetSymbolAddress((void**)&p_w3p2,  w3_p2);
    cudaGetSymbolAddress((void**)&p_w3h1a, w3_h1a);
    cudaGetSymbolAddress((void**)&p_w3h1b, w3_h1b);

    const int GEMM_GRID = (NN + 127) / 128;          // 1563
    const int WCONV_GRID = (128 * HD + 255) / 256;

    // CSR build + norms
    zero_cnt_kernel<<<(NN + 255) / 256, 256>>>();
    hist_kernel<<<(NE + 255) / 256, 256>>>(ei);
    scan1_kernel<<<NBLK, 256>>>();
    scan2_kernel<<<1, 1024>>>();
    scan3_kernel<<<NBLK, 256>>>();
    dis_kernel<<<(NN + 255) / 256, 256>>>();
    fill_kernel<<<(NE + 255) / 256, 256>>>(ei);

    // conversions
    convert_x_kernel<<<(NN * DIN + 255) / 256, 256>>>(x);
    convert_w_kernel<<<(128 * DIN + 255) / 256, 256>>>(in_w, DIN, DIN, 128, p_w3in);
    for (int l = 0; l < NL; l++)
        convert_w_kernel<<<WCONV_GRID, 256>>>(conv_w + (size_t)l * HD * HD, HD, HD, 128,
                                              p_w3conv + (size_t)l * 128 * 3 * HD);
    convert_w_kernel<<<WCONV_GRID, 256>>>(phys_w1, HD, HD, 128, p_w3p1);
    convert_w_kernel<<<WCONV_GRID, 256>>>(phys_w2, HD, HD, 128, p_w3p2);
    convert_w_kernel<<<WCONV_GRID, 256>>>(head_w1,      2 * HD, HD, 128, p_w3h1a);
    convert_w_kernel<<<WCONV_GRID, 256>>>(head_w1 + HD, 2 * HD, HD, 128, p_w3h1b);

    // input projection: h = x @ in_w.T + in_b  (write f32 + bf16)
    gemm_bf16<DIN, false, true, false, false, true, true><<<GEMM_GRID, 256>>>(
        p_x2, p_w3in, in_b, nullptr, nullptr, nullptr, p_h, p_h2, NN);

    // GCN layers: GEMM (hw = h@W.T, f32 only) then fused CSR-agg + silu + LN + residual
    for (int l = 0; l < NL; l++) {
        gemm_bf16<HD, false, false, false, false, true, false><<<GEMM_GRID, 256>>>(
            p_h2, p_w3conv + (size_t)l * 128 * 3 * HD, nullptr,
            nullptr, nullptr, nullptr, p_hw, nullptr, NN);
        agg_silu_ln_kernel<<<(NN + 7) / 8, 256>>>(conv_b + l * HD, ln_g + l * HD, ln_b + l * HD);
    }

    // graph mean pooling over final h
    pool_kernel<<<NG, 128>>>(bv);

    // physics MLP: hw2 = silu(h@W1.T+b1) (bf16 only)
    gemm_bf16<HD, true, true, false, false, false, true><<<GEMM_GRID, 256>>>(
        p_h2, p_w3p1, phys_b1, nullptr, nullptr, nullptr, nullptr, p_hw2, NN);
    // tmp2 = h + hw@W2.T + b2 (bf16 only)
    gemm_bf16<HD, false, true, false, true, false, true><<<GEMM_GRID, 256>>>(
        p_hw2, p_w3p2, phys_b2, nullptr, nullptr, p_h, nullptr, p_tmp2, NN);

    // per-graph precompute: gw = graph_emb @ W1b.T
    gemm_bf16<HD, false, false, false, false, true, false><<<NG / 128, 256>>>(
        p_gemb2, p_w3h1b, nullptr, nullptr, nullptr, nullptr, p_gw, nullptr, NG);

    // hid = silu( tmp @ W1a.T + gw[batch] + b1 )  -> g_hw (f32)
    gemm_bf16<HD, true, true, true, false, true, false><<<GEMM_GRID, 256>>>(
        p_tmp2, p_w3h1a, head_b1, p_gw, bv, nullptr, p_hw, nullptr, NN);

    // out = hid @ w2.T + b2
    head_out_kernel<<<(NN + 7) / 8, 256>>>(head_w2, head_b2, out);
}